// round 15
// baseline (speedup 1.0000x reference)
#include <cuda_runtime.h>
#include <cuda_fp16.h>
#include <cstdint>

// Problem constants
#define T_DIM 512
#define B_DIM 32
#define I_DIM 512
#define H_DIM 512
#define M_DIM (T_DIM * B_DIM)   // 16384
#define N_DIM (3 * H_DIM)       // 1536
#define K_DIM I_DIM             // 512

// gx is stored PRE-SCALED: gates r,z scaled by -log2(e), gate n by -2*log2(e)
#define C1F (-1.4426950408889634f)
#define C2F (-2.8853900817779268f)

// Scratch buffers (static __device__ per allocation rules)
__device__ __align__(16) __half g_gxh[(size_t)M_DIM * N_DIM];              // 48 MB, fp16
__device__ __align__(16) __half g_Ah[(size_t)M_DIM * K_DIM];               // fp16
__device__ __align__(16) __half g_Bh[(size_t)N_DIM * K_DIM];               // fp16
__device__ int g_cnt[128];       // per-M-tile completion counters (12 each)

template <int N>
__device__ __forceinline__ void cp_wait()
{
    asm volatile("cp.async.wait_group %0;" :: "n"(N));
}

__device__ __forceinline__ int ld_cg(const int* p)
{
    int v;
    asm volatile("ld.global.cg.b32 %0, [%1];" : "=r"(v) : "l"(p) : "memory");
    return v;
}

// ---------------------------------------------------------------------------
// Phase 0: fp32 -> fp16 (round-to-nearest) for A and B; zero the counters.
// ---------------------------------------------------------------------------
#define N4X ((M_DIM * K_DIM) / 4)
#define N4W ((N_DIM * K_DIM) / 4)

__global__ void split_kernel(const float* __restrict__ x,
                             const float* __restrict__ W)
{
    if (blockIdx.x == 0 && threadIdx.x < 128) g_cnt[threadIdx.x] = 0;

    int i = blockIdx.x * blockDim.x + threadIdx.x;
    if (i < N4X) {
        float4 v = reinterpret_cast<const float4*>(x)[i];
        __half2 h01 = __halves2half2(__float2half_rn(v.x), __float2half_rn(v.y));
        __half2 h23 = __halves2half2(__float2half_rn(v.z), __float2half_rn(v.w));
        reinterpret_cast<__half2*>(g_Ah)[2 * i]     = h01;
        reinterpret_cast<__half2*>(g_Ah)[2 * i + 1] = h23;
    } else if (i < N4X + N4W) {
        int li = i - N4X;
        float4 v = reinterpret_cast<const float4*>(W)[li];
        __half2 h01 = __halves2half2(__float2half_rn(v.x), __float2half_rn(v.y));
        __half2 h23 = __halves2half2(__float2half_rn(v.z), __float2half_rn(v.w));
        reinterpret_cast<__half2*>(g_Bh)[2 * li]     = h01;
        reinterpret_cast<__half2*>(g_Bh)[2 * li + 1] = h23;
    }
}

// ---------------------------------------------------------------------------
// Fused kernel: bids [0,32) = scan consumers, bids [32, 32+1536) = GEMM tiles.
// GEMM tiles m-tile-major (ascending t); each finished M-tile (12 N-tiles)
// releases 4 timesteps to the scan via g_cnt.
// ---------------------------------------------------------------------------
#define SCAN_CTAS 32
#define GEMM_TILES ((M_DIM / 128) * (N_DIM / 128))   // 128 * 12 = 1536

#define GBM 128
#define GBN 128
#define GBK 32
#define NSTAGE 4
#define LDS_B 80                 // bytes per smem row (64B data + 16B pad)
#define ARR_B (128 * LDS_B)      // 10240 bytes per array
#define STAGE_B (2 * ARR_B)      // 20480 bytes per stage (Ah, Bh)
#define SMEM_TOTAL (NSTAGE * STAGE_B) // 81920

#define SCAN_DEPTH 8
#define SCAN_THREADS 256         // E=2 -> 32 CTAs cover 16384 elements
#define SLOT_U32 (3 * SCAN_THREADS)          // uint32 words per ring slot
#define SLOT_B (SLOT_U32 * 4)                // 3072 bytes per ring slot

__device__ __forceinline__ void ldsm4(uint32_t* r, uint32_t addr)
{
    asm volatile("ldmatrix.sync.aligned.m8n8.x4.shared.b16 {%0,%1,%2,%3}, [%4];"
                 : "=r"(r[0]), "=r"(r[1]), "=r"(r[2]), "=r"(r[3]) : "r"(addr));
}

__device__ __forceinline__ void mma16816(float* c, const uint32_t* a, const uint32_t* b)
{
    asm volatile("mma.sync.aligned.m16n8k16.row.col.f32.f16.f16.f32 "
                 "{%0,%1,%2,%3},{%4,%5,%6,%7},{%8,%9},{%0,%1,%2,%3};"
                 : "+f"(c[0]), "+f"(c[1]), "+f"(c[2]), "+f"(c[3])
                 : "r"(a[0]), "r"(a[1]), "r"(a[2]), "r"(a[3]),
                   "r"(b[0]), "r"(b[1]));
}

__device__ __forceinline__ float fex2(float x)
{
    float r; asm("ex2.approx.f32 %0, %1;" : "=f"(r) : "f"(x)); return r;
}
__device__ __forceinline__ float frcp(float x)
{
    float r; asm("rcp.approx.f32 %0, %1;" : "=f"(r) : "f"(x)); return r;
}

__device__ __forceinline__ float gru_step(float hs, float wrl, float wzl,
                                          float wnl, float g0, float g1, float g2)
{
    float wnl_h = wnl * hs;                       // off critical path
    float r = frcp(1.0f + fex2(fmaf(wrl, hs, g0)));
    float z = frcp(1.0f + fex2(fmaf(wzl, hs, g1)));
    float s2 = frcp(1.0f + fex2(fmaf(r, wnl_h, g2)));
    float n = fmaf(2.0f, s2, -1.0f);
    return fmaf(z, hs - n, n);
}

extern __shared__ char g_smem[];

__device__ void gemm_role(int tile)
{
    const int tid  = threadIdx.x;
    const int lane = tid & 31;
    const int warp = tid >> 5;
    const int wm   = warp & 3;   // 0..3 (M dir)
    const int wn   = warp >> 2;  // 0..1 (N dir)
    const int mt   = tile / (N_DIM / GBN);          // m-tile-major
    const int bn   = (tile % (N_DIM / GBN)) * GBN;
    const int bm   = mt * GBM;

    const uint32_t sbase = (uint32_t)__cvta_generic_to_shared(g_smem);

    float acc[2][8][4];
#pragma unroll
    for (int i = 0; i < 2; ++i)
#pragma unroll
        for (int j = 0; j < 8; ++j)
#pragma unroll
            for (int q = 0; q < 4; ++q) acc[i][j][q] = 0.f;

    auto load_stage = [&](int it, int stage) {
        const int k0 = it * GBK;
        const uint32_t sdst = sbase + stage * STAGE_B;
#pragma unroll
        for (int i = 0; i < 4; ++i) {
            int cid = i * 256 + tid;
            int arr = cid >> 9;
            int rem = cid & 511;
            int r   = rem >> 2;
            int c   = rem & 3;
            const __half* gsrc;
            if (arr == 0) gsrc = g_Ah + (size_t)(bm + r) * K_DIM + k0 + c * 8;
            else          gsrc = g_Bh + (size_t)(bn + r) * K_DIM + k0 + c * 8;
            uint32_t d = sdst + arr * ARR_B + r * LDS_B + c * 16;
            asm volatile("cp.async.cg.shared.global [%0], [%1], 16;"
                         :: "r"(d), "l"(gsrc));
        }
        asm volatile("cp.async.commit_group;");
    };

    auto compute_stage = [&](int stage) {
        const uint32_t sA = sbase + stage * STAGE_B;
#pragma unroll
        for (int s = 0; s < 2; ++s) {
            uint32_t a_hi[2][4];
#pragma unroll
            for (int i = 0; i < 2; ++i) {
                int row  = wm * 32 + i * 16 + (lane & 15);
                int colb = (s * 16 + ((lane >> 4) << 3)) * 2;
                ldsm4(a_hi[i], sA + 0 * ARR_B + row * LDS_B + colb);
            }
            uint32_t b_hi[4][4];
#pragma unroll
            for (int jj = 0; jj < 4; ++jj) {
                int row  = wn * 64 + jj * 16 + ((lane >> 4) << 3) + (lane & 7);
                int colb = (s * 16 + (((lane >> 3) & 1) << 3)) * 2;
                ldsm4(b_hi[jj], sA + 1 * ARR_B + row * LDS_B + colb);
            }
#pragma unroll
            for (int i = 0; i < 2; ++i)
#pragma unroll
                for (int jj = 0; jj < 4; ++jj)
#pragma unroll
                    for (int h2 = 0; h2 < 2; ++h2)
                        mma16816(acc[i][jj * 2 + h2], a_hi[i], &b_hi[jj][h2 * 2]);
        }
    };

    const int NIT = K_DIM / GBK;   // 16
    load_stage(0, 0);
    load_stage(1, 1);
    load_stage(2, 2);

#pragma unroll 1
    for (int it = 0; it < NIT; ++it) {
        if (it < NIT - 2)       cp_wait<2>();
        else if (it == NIT - 2) cp_wait<1>();
        else                    cp_wait<0>();
        __syncthreads();
        if (it + 3 < NIT) load_stage(it + 3, (it + 3) & 3);
        compute_stage(it & 3);
    }

    // Epilogue: scale by gate constant, store fp16 (planar, half2 stores).
    const float sc = (bn >= 2 * H_DIM) ? C2F : C1F;
#pragma unroll
    for (int i = 0; i < 2; ++i)
#pragma unroll
        for (int j = 0; j < 8; ++j) {
            int r0 = bm + wm * 32 + i * 16 + (lane >> 2);
            int c0 = bn + wn * 64 + j * 8 + ((lane & 3) << 1);
            __half2 v01 = __floats2half2_rn(sc * acc[i][j][0], sc * acc[i][j][1]);
            __half2 v23 = __floats2half2_rn(sc * acc[i][j][2], sc * acc[i][j][3]);
            *reinterpret_cast<__half2*>(g_gxh + (size_t)r0 * N_DIM + c0)       = v01;
            *reinterpret_cast<__half2*>(g_gxh + (size_t)(r0 + 8) * N_DIM + c0) = v23;
        }

    // Publish: all stores visible, then one arrival on the M-tile counter.
    __threadfence();
    __syncthreads();
    if (tid == 0) atomicAdd(&g_cnt[mt], 1);
}

__device__ void scan_role(const float* __restrict__ h0,
                          const float* __restrict__ w_hh,
                          float* __restrict__ out)
{
    uint32_t* sbufu = reinterpret_cast<uint32_t*>(g_smem);   // [DEPTH][3][256]

    const int tid = threadIdx.x;
    const int e0  = (blockIdx.x * SCAN_THREADS + tid) * 2;    // even
    const int b   = e0 >> 9;
    const int h   = e0 & (H_DIM - 1);

    const float2 wr2 = *reinterpret_cast<const float2*>(w_hh + h);
    const float2 wz2 = *reinterpret_cast<const float2*>(w_hh + H_DIM + h);
    const float2 wn2 = *reinterpret_cast<const float2*>(w_hh + 2 * H_DIM + h);
    const float wrlx = C1F * wr2.x, wrly = C1F * wr2.y;
    const float wzlx = C1F * wz2.x, wzly = C1F * wz2.y;
    const float wnlx = C2F * wn2.x, wnly = C2F * wn2.y;

    float2 hs = *reinterpret_cast<const float2*>(h0 + e0);

    const __half* gbase = g_gxh + (size_t)b * N_DIM + h;
    const uint32_t sb = (uint32_t)__cvta_generic_to_shared(sbufu) + tid * 4;

    int ready_mt = -1;
    auto issue = [&](int t) {
        if (t < T_DIM) {
            const int mt = t >> 2;
            if (mt > ready_mt) {
                // lane0 polls relaxed; warp broadcast; single fence per release
                if ((tid & 31) == 0)
                    while (ld_cg(&g_cnt[mt]) < (N_DIM / GBN)) __nanosleep(64);
                __syncwarp();
                asm volatile("fence.acq_rel.gpu;" ::: "memory");
                ready_mt = mt;
            }
            const __half* p = gbase + (size_t)t * (B_DIM * N_DIM);
            uint32_t d = sb + (t & (SCAN_DEPTH - 1)) * SLOT_B;
            asm volatile("cp.async.ca.shared.global [%0], [%1], 4;" :: "r"(d),        "l"(p));
            asm volatile("cp.async.ca.shared.global [%0], [%1], 4;" :: "r"(d + 1024), "l"(p + H_DIM));
            asm volatile("cp.async.ca.shared.global [%0], [%1], 4;" :: "r"(d + 2048), "l"(p + 2 * H_DIM));
        }
        asm volatile("cp.async.commit_group;");
    };

    // Prologue: issue steps 0..6 (7 groups), wait step 0, preload its regs.
#pragma unroll 1
    for (int t = 0; t < SCAN_DEPTH - 1; ++t) issue(t);
    cp_wait<SCAN_DEPTH - 2>();

    float2 cur0 = __half22float2(*reinterpret_cast<__half2*>(&sbufu[0 * 256 + tid]));
    float2 cur1 = __half22float2(*reinterpret_cast<__half2*>(&sbufu[1 * 256 + tid]));
    float2 cur2 = __half22float2(*reinterpret_cast<__half2*>(&sbufu[2 * 256 + tid]));

    float* o = out + e0;
#pragma unroll 1
    for (int t = 0; t < T_DIM; ++t) {
        issue(t + SCAN_DEPTH - 1);
        if (t < T_DIM - SCAN_DEPTH) cp_wait<SCAN_DEPTH - 2>();
        else                        cp_wait<0>();

        const int sn = (t + 1) & (SCAN_DEPTH - 1);
        float2 nxt0 = __half22float2(*reinterpret_cast<__half2*>(&sbufu[sn * SLOT_U32 + 0 * 256 + tid]));
        float2 nxt1 = __half22float2(*reinterpret_cast<__half2*>(&sbufu[sn * SLOT_U32 + 1 * 256 + tid]));
        float2 nxt2 = __half22float2(*reinterpret_cast<__half2*>(&sbufu[sn * SLOT_U32 + 2 * 256 + tid]));

        hs.x = gru_step(hs.x, wrlx, wzlx, wnlx, cur0.x, cur1.x, cur2.x);
        hs.y = gru_step(hs.y, wrly, wzly, wnly, cur0.y, cur1.y, cur2.y);

        *reinterpret_cast<float2*>(o) = hs;
        o += B_DIM * H_DIM;

        cur0 = nxt0; cur1 = nxt1; cur2 = nxt2;
    }

    *reinterpret_cast<float2*>(out + (size_t)T_DIM * B_DIM * H_DIM + e0) = hs;
}

__global__ __launch_bounds__(256)
void fused_kernel(const float* __restrict__ h0,
                  const float* __restrict__ w_hh,
                  float* __restrict__ out)
{
    if (blockIdx.x < SCAN_CTAS) scan_role(h0, w_hh, out);
    else                        gemm_role(blockIdx.x - SCAN_CTAS);
}

// ---------------------------------------------------------------------------
// Launch.  Inputs: x (T*B*I), h0 (B*H), W_ih (3H*I), w_hh (3*H). Output fp32.
// ---------------------------------------------------------------------------
extern "C" void kernel_launch(void* const* d_in, const int* in_sizes, int n_in,
                              void* d_out, int out_size)
{
    const float* x    = (const float*)d_in[0];
    const float* h0   = (const float*)d_in[1];
    const float* W_ih = (const float*)d_in[2];
    const float* w_hh = (const float*)d_in[3];
    float* out = (float*)d_out;

    cudaFuncSetAttribute(fused_kernel,
                         cudaFuncAttributeMaxDynamicSharedMemorySize, SMEM_TOTAL);

    int n4 = N4X + N4W;
    split_kernel<<<(n4 + 255) / 256, 256>>>(x, W_ih);

    fused_kernel<<<SCAN_CTAS + GEMM_TILES, 256, SMEM_TOTAL>>>(h0, w_hh, out);
}

// round 16
// speedup vs baseline: 1.4235x; 1.4235x over previous
#include <cuda_runtime.h>
#include <cuda_fp16.h>
#include <cstdint>

// Problem constants
#define T_DIM 512
#define B_DIM 32
#define I_DIM 512
#define H_DIM 512
#define M_DIM (T_DIM * B_DIM)   // 16384
#define N_DIM (3 * H_DIM)       // 1536
#define K_DIM I_DIM             // 512

// gx is stored PRE-SCALED: gates r,z scaled by -log2(e), gate n by -2*log2(e)
#define C1F (-1.4426950408889634f)
#define C2F (-2.8853900817779268f)

// Scratch buffers (static __device__ per allocation rules)
__device__ __align__(16) __half g_gxh[(size_t)M_DIM * N_DIM];              // 48 MB fp16
__device__ __align__(16) __half g_Ah[(size_t)M_DIM * K_DIM];               // fp16
__device__ __align__(16) __half g_Bh[(size_t)N_DIM * K_DIM];               // fp16
__device__ int g_cnt[128];       // per-M-tile completion counters (12 each)

template <int N>
__device__ __forceinline__ void cp_wait()
{
    asm volatile("cp.async.wait_group %0;" :: "n"(N));
}

__device__ __forceinline__ int ld_acq(const int* p)
{
    int v;
    asm volatile("ld.acquire.gpu.global.b32 %0, [%1];" : "=r"(v) : "l"(p) : "memory");
    return v;
}

// ---------------------------------------------------------------------------
// Phase 0: fp32 -> fp16 (round-to-nearest) for A and B; zero the counters.
// ---------------------------------------------------------------------------
#define N4X ((M_DIM * K_DIM) / 4)
#define N4W ((N_DIM * K_DIM) / 4)

__global__ void split_kernel(const float* __restrict__ x,
                             const float* __restrict__ W)
{
    if (blockIdx.x == 0 && threadIdx.x < 128) g_cnt[threadIdx.x] = 0;

    int i = blockIdx.x * blockDim.x + threadIdx.x;
    if (i < N4X) {
        float4 v = reinterpret_cast<const float4*>(x)[i];
        __half2 h01 = __halves2half2(__float2half_rn(v.x), __float2half_rn(v.y));
        __half2 h23 = __halves2half2(__float2half_rn(v.z), __float2half_rn(v.w));
        reinterpret_cast<__half2*>(g_Ah)[2 * i]     = h01;
        reinterpret_cast<__half2*>(g_Ah)[2 * i + 1] = h23;
    } else if (i < N4X + N4W) {
        int li = i - N4X;
        float4 v = reinterpret_cast<const float4*>(W)[li];
        __half2 h01 = __halves2half2(__float2half_rn(v.x), __float2half_rn(v.y));
        __half2 h23 = __halves2half2(__float2half_rn(v.z), __float2half_rn(v.w));
        reinterpret_cast<__half2*>(g_Bh)[2 * li]     = h01;
        reinterpret_cast<__half2*>(g_Bh)[2 * li + 1] = h23;
    }
}

// ---------------------------------------------------------------------------
// Fused kernel: bids [0,32) = scan consumers, bids [32, 32+1536) = GEMM tiles.
// GEMM tiles m-tile-major (ascending t); each finished M-tile (12 N-tiles)
// releases 4 timesteps to the scan via g_cnt.
// ---------------------------------------------------------------------------
#define SCAN_CTAS 32
#define GEMM_TILES ((M_DIM / 128) * (N_DIM / 128))   // 128 * 12 = 1536

#define GBM 128
#define GBN 128
#define GBK 32
#define NSTAGE 4
#define LDS_B 80                 // bytes per smem row (64B data + 16B pad)
#define ARR_B (128 * LDS_B)      // 10240 bytes per array
#define STAGE_B (2 * ARR_B)      // 20480 bytes per stage (Ah, Bh)
#define SMEM_TOTAL (NSTAGE * STAGE_B) // 81920

#define SCAN_DEPTH 8
#define SCAN_THREADS 256         // E=2 -> 32 CTAs cover 16384 elements
#define SLOT_U32 (3 * SCAN_THREADS)          // uint32 words per ring slot
#define SLOT_B (SLOT_U32 * 4)                // 3072 bytes per ring slot

__device__ __forceinline__ void ldsm4(uint32_t* r, uint32_t addr)
{
    asm volatile("ldmatrix.sync.aligned.m8n8.x4.shared.b16 {%0,%1,%2,%3}, [%4];"
                 : "=r"(r[0]), "=r"(r[1]), "=r"(r[2]), "=r"(r[3]) : "r"(addr));
}

__device__ __forceinline__ void mma16816(float* c, const uint32_t* a, const uint32_t* b)
{
    asm volatile("mma.sync.aligned.m16n8k16.row.col.f32.f16.f16.f32 "
                 "{%0,%1,%2,%3},{%4,%5,%6,%7},{%8,%9},{%0,%1,%2,%3};"
                 : "+f"(c[0]), "+f"(c[1]), "+f"(c[2]), "+f"(c[3])
                 : "r"(a[0]), "r"(a[1]), "r"(a[2]), "r"(a[3]),
                   "r"(b[0]), "r"(b[1]));
}

__device__ __forceinline__ float fex2(float x)
{
    float r; asm("ex2.approx.f32 %0, %1;" : "=f"(r) : "f"(x)); return r;
}
__device__ __forceinline__ float frcp(float x)
{
    float r; asm("rcp.approx.f32 %0, %1;" : "=f"(r) : "f"(x)); return r;
}

__device__ __forceinline__ float gru_step(float hs, float wrl, float wzl,
                                          float wnl, float g0, float g1, float g2)
{
    float wnl_h = wnl * hs;                       // off critical path
    float r = frcp(1.0f + fex2(fmaf(wrl, hs, g0)));
    float z = frcp(1.0f + fex2(fmaf(wzl, hs, g1)));
    float s2 = frcp(1.0f + fex2(fmaf(r, wnl_h, g2)));
    float n = fmaf(2.0f, s2, -1.0f);
    return fmaf(z, hs - n, n);
}

extern __shared__ char g_smem[];

__device__ void gemm_role(int tile)
{
    const int tid  = threadIdx.x;
    const int lane = tid & 31;
    const int warp = tid >> 5;
    const int wm   = warp & 3;   // 0..3 (M dir)
    const int wn   = warp >> 2;  // 0..1 (N dir)
    const int mt   = tile / (N_DIM / GBN);          // m-tile-major
    const int bn   = (tile % (N_DIM / GBN)) * GBN;
    const int bm   = mt * GBM;

    const uint32_t sbase = (uint32_t)__cvta_generic_to_shared(g_smem);

    float acc[2][8][4];
#pragma unroll
    for (int i = 0; i < 2; ++i)
#pragma unroll
        for (int j = 0; j < 8; ++j)
#pragma unroll
            for (int q = 0; q < 4; ++q) acc[i][j][q] = 0.f;

    auto load_stage = [&](int it, int stage) {
        const int k0 = it * GBK;
        const uint32_t sdst = sbase + stage * STAGE_B;
#pragma unroll
        for (int i = 0; i < 4; ++i) {
            int cid = i * 256 + tid;
            int arr = cid >> 9;
            int rem = cid & 511;
            int r   = rem >> 2;
            int c   = rem & 3;
            const __half* gsrc;
            if (arr == 0) gsrc = g_Ah + (size_t)(bm + r) * K_DIM + k0 + c * 8;
            else          gsrc = g_Bh + (size_t)(bn + r) * K_DIM + k0 + c * 8;
            uint32_t d = sdst + arr * ARR_B + r * LDS_B + c * 16;
            asm volatile("cp.async.cg.shared.global [%0], [%1], 16;"
                         :: "r"(d), "l"(gsrc));
        }
        asm volatile("cp.async.commit_group;");
    };

    auto compute_stage = [&](int stage) {
        const uint32_t sA = sbase + stage * STAGE_B;
#pragma unroll
        for (int s = 0; s < 2; ++s) {
            uint32_t a_hi[2][4];
#pragma unroll
            for (int i = 0; i < 2; ++i) {
                int row  = wm * 32 + i * 16 + (lane & 15);
                int colb = (s * 16 + ((lane >> 4) << 3)) * 2;
                ldsm4(a_hi[i], sA + 0 * ARR_B + row * LDS_B + colb);
            }
            uint32_t b_hi[4][4];
#pragma unroll
            for (int jj = 0; jj < 4; ++jj) {
                int row  = wn * 64 + jj * 16 + ((lane >> 4) << 3) + (lane & 7);
                int colb = (s * 16 + (((lane >> 3) & 1) << 3)) * 2;
                ldsm4(b_hi[jj], sA + 1 * ARR_B + row * LDS_B + colb);
            }
#pragma unroll
            for (int i = 0; i < 2; ++i)
#pragma unroll
                for (int jj = 0; jj < 4; ++jj)
#pragma unroll
                    for (int h2 = 0; h2 < 2; ++h2)
                        mma16816(acc[i][jj * 2 + h2], a_hi[i], &b_hi[jj][h2 * 2]);
        }
    };

    const int NIT = K_DIM / GBK;   // 16
    load_stage(0, 0);
    load_stage(1, 1);
    load_stage(2, 2);

#pragma unroll 1
    for (int it = 0; it < NIT; ++it) {
        if (it < NIT - 2)       cp_wait<2>();
        else if (it == NIT - 2) cp_wait<1>();
        else                    cp_wait<0>();
        __syncthreads();
        if (it + 3 < NIT) load_stage(it + 3, (it + 3) & 3);
        compute_stage(it & 3);
    }

    // Epilogue: scale by gate constant, store fp16 (planar, half2 stores).
    const float sc = (bn >= 2 * H_DIM) ? C2F : C1F;
#pragma unroll
    for (int i = 0; i < 2; ++i)
#pragma unroll
        for (int j = 0; j < 8; ++j) {
            int r0 = bm + wm * 32 + i * 16 + (lane >> 2);
            int c0 = bn + wn * 64 + j * 8 + ((lane & 3) << 1);
            __half2 v01 = __floats2half2_rn(sc * acc[i][j][0], sc * acc[i][j][1]);
            __half2 v23 = __floats2half2_rn(sc * acc[i][j][2], sc * acc[i][j][3]);
            *reinterpret_cast<__half2*>(g_gxh + (size_t)r0 * N_DIM + c0)       = v01;
            *reinterpret_cast<__half2*>(g_gxh + (size_t)(r0 + 8) * N_DIM + c0) = v23;
        }

    // Publish: all stores visible, then one arrival on the M-tile counter.
    __threadfence();
    __syncthreads();
    if (tid == 0) atomicAdd(&g_cnt[mt], 1);
}

__device__ void scan_role(const float* __restrict__ h0,
                          const float* __restrict__ w_hh,
                          float* __restrict__ out)
{
    uint32_t* sbufu = reinterpret_cast<uint32_t*>(g_smem);   // [DEPTH][3][256]

    const int tid = threadIdx.x;
    const int e0  = (blockIdx.x * SCAN_THREADS + tid) * 2;    // even
    const int b   = e0 >> 9;
    const int h   = e0 & (H_DIM - 1);

    const float2 wr2 = *reinterpret_cast<const float2*>(w_hh + h);
    const float2 wz2 = *reinterpret_cast<const float2*>(w_hh + H_DIM + h);
    const float2 wn2 = *reinterpret_cast<const float2*>(w_hh + 2 * H_DIM + h);
    const float wrlx = C1F * wr2.x, wrly = C1F * wr2.y;
    const float wzlx = C1F * wz2.x, wzly = C1F * wz2.y;
    const float wnlx = C2F * wn2.x, wnly = C2F * wn2.y;

    float2 hs = *reinterpret_cast<const float2*>(h0 + e0);

    const __half* gbase = g_gxh + (size_t)b * N_DIM + h;
    const uint32_t sb = (uint32_t)__cvta_generic_to_shared(sbufu) + tid * 4;

    int ready_mt = -1;
    auto issue = [&](int t) {
        if (t < T_DIM) {
            const int mt = t >> 2;
            if (mt > ready_mt) {
                // R14-proven release wait: all threads, acquire folded into poll
                while (ld_acq(&g_cnt[mt]) < (N_DIM / GBN)) __nanosleep(64);
                ready_mt = mt;
            }
            const __half* p = gbase + (size_t)t * (B_DIM * N_DIM);
            uint32_t d = sb + (t & (SCAN_DEPTH - 1)) * SLOT_B;
            asm volatile("cp.async.ca.shared.global [%0], [%1], 4;" :: "r"(d),        "l"(p));
            asm volatile("cp.async.ca.shared.global [%0], [%1], 4;" :: "r"(d + 1024), "l"(p + H_DIM));
            asm volatile("cp.async.ca.shared.global [%0], [%1], 4;" :: "r"(d + 2048), "l"(p + 2 * H_DIM));
        }
        asm volatile("cp.async.commit_group;");
    };

    // Prologue: issue steps 0..6 (7 groups), wait step 0, preload its regs.
#pragma unroll 1
    for (int t = 0; t < SCAN_DEPTH - 1; ++t) issue(t);
    cp_wait<SCAN_DEPTH - 2>();

    float2 cur0 = __half22float2(*reinterpret_cast<__half2*>(&sbufu[0 * 256 + tid]));
    float2 cur1 = __half22float2(*reinterpret_cast<__half2*>(&sbufu[1 * 256 + tid]));
    float2 cur2 = __half22float2(*reinterpret_cast<__half2*>(&sbufu[2 * 256 + tid]));

    float* o = out + e0;
#pragma unroll 1
    for (int t = 0; t < T_DIM; ++t) {
        issue(t + SCAN_DEPTH - 1);
        if (t < T_DIM - SCAN_DEPTH) cp_wait<SCAN_DEPTH - 2>();
        else                        cp_wait<0>();

        const int sn = (t + 1) & (SCAN_DEPTH - 1);
        float2 nxt0 = __half22float2(*reinterpret_cast<__half2*>(&sbufu[sn * SLOT_U32 + 0 * 256 + tid]));
        float2 nxt1 = __half22float2(*reinterpret_cast<__half2*>(&sbufu[sn * SLOT_U32 + 1 * 256 + tid]));
        float2 nxt2 = __half22float2(*reinterpret_cast<__half2*>(&sbufu[sn * SLOT_U32 + 2 * 256 + tid]));

        hs.x = gru_step(hs.x, wrlx, wzlx, wnlx, cur0.x, cur1.x, cur2.x);
        hs.y = gru_step(hs.y, wrly, wzly, wnly, cur0.y, cur1.y, cur2.y);

        *reinterpret_cast<float2*>(o) = hs;
        o += B_DIM * H_DIM;

        cur0 = nxt0; cur1 = nxt1; cur2 = nxt2;
    }

    *reinterpret_cast<float2*>(out + (size_t)T_DIM * B_DIM * H_DIM + e0) = hs;
}

__global__ __launch_bounds__(256)
void fused_kernel(const float* __restrict__ h0,
                  const float* __restrict__ w_hh,
                  float* __restrict__ out)
{
    if (blockIdx.x < SCAN_CTAS) scan_role(h0, w_hh, out);
    else                        gemm_role(blockIdx.x - SCAN_CTAS);
}

// ---------------------------------------------------------------------------
// Launch.  Inputs: x (T*B*I), h0 (B*H), W_ih (3H*I), w_hh (3*H). Output fp32.
// ---------------------------------------------------------------------------
extern "C" void kernel_launch(void* const* d_in, const int* in_sizes, int n_in,
                              void* d_out, int out_size)
{
    const float* x    = (const float*)d_in[0];
    const float* h0   = (const float*)d_in[1];
    const float* W_ih = (const float*)d_in[2];
    const float* w_hh = (const float*)d_in[3];
    float* out = (float*)d_out;

    cudaFuncSetAttribute(fused_kernel,
                         cudaFuncAttributeMaxDynamicSharedMemorySize, SMEM_TOTAL);

    int n4 = N4X + N4W;
    split_kernel<<<(n4 + 255) / 256, 256>>>(x, W_ih);

    fused_kernel<<<SCAN_CTAS + GEMM_TILES, 256, SMEM_TOTAL>>>(h0, w_hh, out);
}